// round 13
// baseline (speedup 1.0000x reference)
#include <cuda_runtime.h>
#include <cuda_bf16.h>

#define BATCH 8
#define CHANS 4
#define H 512
#define W 512
#define NPIX (BATCH * H * W)          // 2,097,152
#define NROWS (BATCH * H)             // 4096
#define LOSS_BLOCKS (BATCH * (H / 4)) // 1024

typedef unsigned long long u64;
#define FARW 0x7f7f7f7fu

// Scratch: per-pixel horizontal distances (byte pairs: fg, bg).
__device__ uchar2 g_rcol[NPIX];
__device__ double g_bsum[LOSS_BLOCKS];

// ---------------------------------------------------------------------------
// Kernel 1: horizontal distance to nearest opposite-class pixel. (R10/R12)
// 4 rows/block (256 thr), 64 lanes/row, 8 px/lane; 32-bit funnel-shift search.
// ---------------------------------------------------------------------------
__global__ void rowdist_kernel(const int4* __restrict__ yt4) {
    __shared__ unsigned m32[4][20];   // [0] guard, [1..16] mask, [17..19] guards
    const int tid = threadIdx.x;
    const int r  = tid >> 6;              // row in block 0..3
    const int gl = tid & 63;              // byte index, pixels 8gl..8gl+7
    const int row = blockIdx.x * 4 + r;

    const int4* pp = yt4 + (size_t)row * 128 + gl * 2;
    int4 a = pp[0], b = pp[1];

    unsigned ta = __byte_perm((unsigned)a.x, (unsigned)a.y, 0x4040);
    unsigned tb = __byte_perm((unsigned)a.z, (unsigned)a.w, 0x4040);
    unsigned ua = __byte_perm(ta, tb, 0x5410);
    unsigned tc = __byte_perm((unsigned)b.x, (unsigned)b.y, 0x4040);
    unsigned td = __byte_perm((unsigned)b.z, (unsigned)b.w, 0x4040);
    unsigned ub = __byte_perm(tc, td, 0x5410);
    ua = (ua | (ua >> 1)) & 0x01010101u;
    ub = (ub | (ub >> 1)) & 0x01010101u;
    unsigned m8 = (((ua * 0x01020408u) >> 24) & 0xFu)
                | (((ub * 0x01020408u) >> 20) & 0xF0u);

    if (tid < 4) { m32[tid][0] = 0u; }
    if (tid >= 4 && tid < 16) { m32[tid & 3][17 + (tid >> 2) - 1] = 0u; }
    ((unsigned char*)&m32[r][1])[gl] = (unsigned char)m8;
    __syncthreads();

    const unsigned* base = &m32[r][gl >> 2];
    unsigned m0 = base[0], m1 = base[1], m2 = base[2], m3 = base[3];
    unsigned e0 = m0 ^ __funnelshift_r(m0, m1, 1);
    unsigned e1 = m1 ^ __funnelshift_r(m1, m2, 1);
    unsigned e2 = m2 ^ __funnelshift_r(m2, m3, 1);
    if (gl < 4)   e0 &= 0x7FFFFFFFu;      // fake transition guard|pixel0
    if (gl >= 60) e1 &= 0x7FFFFFFFu;      // fake transition pixel511|guard

    const int pb = (gl & 3) * 8;
    u64 out[2] = {0ull, 0ull};
    #pragma unroll
    for (int j = 0; j < 8; ++j) {
        const int p = pb + j;
        unsigned R32 = __funnelshift_r(e1, e2, p);
        unsigned L32 = __funnelshift_r(e0, e1, p);
        int rd = __ffs((int)(R32 | 0x80000000u));    // 1..32 (32 = far)
        int ld = __clz((int)(L32 | 1u)) + 1;         // 1..32 (32 = far)
        unsigned e = (unsigned)min(rd, ld);
        unsigned pair = ((m1 >> p) & 1u) ? (e << 8) : e;
        out[j >> 2] |= (u64)pair << (16 * (j & 3));
    }
    ((ulonglong2*)g_rcol)[(size_t)row * 64 + gl] = make_ulonglong2(out[0], out[1]);
}

__device__ __forceinline__ uint4 vmin44(uint4 a, uint4 b) {
    return make_uint4(__vminu4(a.x, b.x), __vminu4(a.y, b.y),
                      __vminu4(a.z, b.z), __vminu4(a.w, b.w));
}
__device__ __forceinline__ uint4 vmax4s(uint4 a, unsigned d) {
    return make_uint4(__vmaxu4(a.x, d), __vmaxu4(a.y, d),
                      __vmaxu4(a.z, d), __vmaxu4(a.w, d));
}

// ---------------------------------------------------------------------------
// Kernel 2: vertical combine (d=1..4 prefetched & unconditional; checked loop
// only for the ~1e-4-probability deep cases) + softmax + weighted SE +
// block reduction. 4 rows/block, 256 thr, 8 px/thread.
// ---------------------------------------------------------------------------
__global__ void loss_kernel(const float4* __restrict__ logits4) {
    const int o = threadIdx.x & 63;       // x-octet 0..63 (pixels 8o..8o+7)
    const int r = threadIdx.x >> 6;       // row in block 0..3
    const int y = blockIdx.y * 4 + r;
    const int b = blockIdx.z;

    // ---- all independent loads issued up front: 8 logits + self + 8 taps ----
    const float4* lp = logits4 + ((size_t)b * CHANS * H + y) * 128 + o * 2;
    float4 La0 = lp[0];
    float4 La1 = lp[(size_t)H * 128];
    float4 La2 = lp[2 * (size_t)H * 128];
    float4 La3 = lp[3 * (size_t)H * 128];
    float4 Lb0 = lp[1];
    float4 Lb1 = lp[(size_t)H * 128 + 1];
    float4 Lb2 = lp[2 * (size_t)H * 128 + 1];
    float4 Lb3 = lp[3 * (size_t)H * 128 + 1];

    const uint4* col = (const uint4*)g_rcol + (size_t)b * H * 64 + o;
    const uint4 FARQ = make_uint4(FARW, FARW, FARW, FARW);
    uint4 self = col[(size_t)y * 64];
    uint4 up1 = (y - 1 >= 0) ? col[(size_t)(y - 1) * 64] : FARQ;
    uint4 dn1 = (y + 1 <  H) ? col[(size_t)(y + 1) * 64] : FARQ;
    uint4 up2 = (y - 2 >= 0) ? col[(size_t)(y - 2) * 64] : FARQ;
    uint4 dn2 = (y + 2 <  H) ? col[(size_t)(y + 2) * 64] : FARQ;
    uint4 up3 = (y - 3 >= 0) ? col[(size_t)(y - 3) * 64] : FARQ;
    uint4 dn3 = (y + 3 <  H) ? col[(size_t)(y + 3) * 64] : FARQ;
    uint4 up4 = (y - 4 >= 0) ? col[(size_t)(y - 4) * 64] : FARQ;
    uint4 dn4 = (y + 4 <  H) ? col[(size_t)(y + 4) * 64] : FARQ;

    // ---- softmax for all 8 pixels while taps fly ----
    float gp[8];
    {
        float l0[8] = {La0.x, La0.y, La0.z, La0.w, Lb0.x, Lb0.y, Lb0.z, Lb0.w};
        float l1[8] = {La1.x, La1.y, La1.z, La1.w, Lb1.x, Lb1.y, Lb1.z, Lb1.w};
        float l2[8] = {La2.x, La2.y, La2.z, La2.w, Lb2.x, Lb2.y, Lb2.z, Lb2.w};
        float l3[8] = {La3.x, La3.y, La3.z, La3.w, Lb3.x, Lb3.y, Lb3.z, Lb3.w};
        #pragma unroll
        for (int k = 0; k < 8; ++k) {
            float hi  = fmaxf(l1[k], l2[k]);
            float lo  = fminf(l1[k], l2[k]);
            float aa  = fmaxf(hi, l3[k]);
            float sec = fminf(hi, l3[k]);
            float sum = 1.0f + __expf(lo - aa) + __expf(sec - aa) + __expf(l0[k] - aa);
            gp[k] = 1.0f / sum;
        }
    }

    // ---- steps d=1..4 unconditional, branch-free ----
    uint4 s = self;
    s = vmin44(s, vmin44(vmax4s(vmin44(up1, dn1), 0x01010101u),
                         vmax4s(vmin44(up2, dn2), 0x02020202u)));
    s = vmin44(s, vmin44(vmax4s(vmin44(up3, dn3), 0x03030303u),
                         vmax4s(vmin44(up4, dn4), 0x04040404u)));

    // ---- rare deep cases: checked double-steps from d=5 ----
    #pragma unroll 1
    for (int d = 5; d <= 29; d += 2) {
        unsigned mm = __vmaxu4(__vmaxu4(s.x, s.y), __vmaxu4(s.z, s.w));
        if (((mm + (128 - d) * 0x01010101u) & 0x80808080u) == 0u) break; // all <= d-1
        uint4 u1 = (y - d     >= 0) ? col[(size_t)(y - d)     * 64] : FARQ;
        uint4 d1 = (y + d     <  H) ? col[(size_t)(y + d)     * 64] : FARQ;
        uint4 u2 = (y - d - 1 >= 0) ? col[(size_t)(y - d - 1) * 64] : FARQ;
        uint4 d2 = (y + d + 1 <  H) ? col[(size_t)(y + d + 1) * 64] : FARQ;
        unsigned dd1 = (unsigned)d * 0x01010101u;
        unsigned dd2 = dd1 + 0x01010101u;
        s = vmin44(s, vmin44(vmax4s(vmin44(u1, d1), dd1),
                             vmax4s(vmin44(u2, d2), dd2)));
    }

    // ---- combine: integer wmap, fp32 error ----
    unsigned sw[4] = {s.x, s.y, s.z, s.w};
    float v = 0.0f;
    #pragma unroll
    for (int k = 0; k < 8; ++k) {
        unsigned w = sw[k >> 1] >> (16 * (k & 1));
        unsigned f = w & 255u;
        unsigned g = (w >> 8) & 255u;
        int df2 = (f <= 30u) ? (int)(f * f) : 40000;
        int dg2 = (g <= 30u) ? (int)(g * g) : 40000;
        float wmap = (float)(df2 + dg2);
        float gt = (f == 0u) ? 1.0f : 0.0f;
        float diff = gp[k] - gt;
        v += diff * diff * wmap;
    }

    // ---- deterministic block reduction (8 warps) ----
    #pragma unroll
    for (int oo = 16; oo > 0; oo >>= 1) v += __shfl_down_sync(0xFFFFFFFFu, v, oo);
    __shared__ float wsum[8];
    int lane = threadIdx.x & 31, wid = threadIdx.x >> 5;
    if (lane == 0) wsum[wid] = v;
    __syncthreads();
    if (threadIdx.x == 0) {
        double sd = 0.0;
        #pragma unroll
        for (int i = 0; i < 8; ++i) sd += (double)wsum[i];
        g_bsum[blockIdx.z * gridDim.y + blockIdx.y] = sd;
    }
}

// Kernel 3: deterministic final reduction + mean. 1024 threads, 1 elem each.
__global__ void final_kernel(float* __restrict__ out) {
    __shared__ double sh[1024];
    sh[threadIdx.x] = g_bsum[threadIdx.x];
    __syncthreads();
    #pragma unroll
    for (int o = 512; o > 0; o >>= 1) {
        if (threadIdx.x < o) sh[threadIdx.x] += sh[threadIdx.x + o];
        __syncthreads();
    }
    if (threadIdx.x == 0) out[0] = (float)(sh[0] / (double)NPIX);
}

extern "C" void kernel_launch(void* const* d_in, const int* in_sizes, int n_in,
                              void* d_out, int out_size) {
    const float* logits = (const float*)d_in[0];
    const int*   y_true = (const int*)d_in[1];
    float*       out    = (float*)d_out;

    rowdist_kernel<<<NROWS / 4, 256>>>((const int4*)y_true);

    dim3 blk(256, 1, 1);
    dim3 grd(1, H / 4, BATCH);
    loss_kernel<<<grd, blk>>>((const float4*)logits);

    final_kernel<<<1, 1024>>>(out);
}

// round 14
// speedup vs baseline: 1.1219x; 1.1219x over previous
#include <cuda_runtime.h>
#include <cuda_bf16.h>

#define BATCH 8
#define CHANS 4
#define H 512
#define W 512
#define NPIX (BATCH * H * W)          // 2,097,152
#define NROWS (BATCH * H)             // 4096
#define LOSS_BLOCKS (BATCH * (H / 4)) // 1024

typedef unsigned long long u64;
#define FARW 0x7f7f7f7fu

// Scratch: per-pixel horizontal distances (byte pairs: fg, bg).
__device__ uchar2 g_rcol[NPIX];
__device__ double g_bsum[LOSS_BLOCKS];

// ---------------------------------------------------------------------------
// Kernel 1: horizontal distance to nearest opposite-class pixel.
// 4 rows/block (256 thr), 64 lanes/row, 8 px/lane; 32-bit funnel-shift search.
// Results packed as four u32 (two pixel-pairs each), one uint4 store.
// ---------------------------------------------------------------------------
__global__ void rowdist_kernel(const int4* __restrict__ yt4) {
    __shared__ unsigned m32[4][20];   // [0] guard, [1..16] mask, [17..19] guards
    const int tid = threadIdx.x;
    const int r  = tid >> 6;              // row in block 0..3
    const int gl = tid & 63;              // byte index, pixels 8gl..8gl+7
    const int row = blockIdx.x * 4 + r;

    const int4* pp = yt4 + (size_t)row * 128 + gl * 2;
    int4 a = pp[0], b = pp[1];

    unsigned ta = __byte_perm((unsigned)a.x, (unsigned)a.y, 0x4040);
    unsigned tb = __byte_perm((unsigned)a.z, (unsigned)a.w, 0x4040);
    unsigned ua = __byte_perm(ta, tb, 0x5410);
    unsigned tc = __byte_perm((unsigned)b.x, (unsigned)b.y, 0x4040);
    unsigned td = __byte_perm((unsigned)b.z, (unsigned)b.w, 0x4040);
    unsigned ub = __byte_perm(tc, td, 0x5410);
    ua = (ua | (ua >> 1)) & 0x01010101u;
    ub = (ub | (ub >> 1)) & 0x01010101u;
    unsigned m8 = (((ua * 0x01020408u) >> 24) & 0xFu)
                | (((ub * 0x01020408u) >> 20) & 0xF0u);

    if (tid < 4) { m32[tid][0] = 0u; }
    if (tid >= 4 && tid < 16) { m32[tid & 3][17 + (tid >> 2) - 1] = 0u; }
    ((unsigned char*)&m32[r][1])[gl] = (unsigned char)m8;
    __syncthreads();

    const unsigned* base = &m32[r][gl >> 2];
    unsigned m0 = base[0], m1 = base[1], m2 = base[2], m3 = base[3];
    unsigned e0 = m0 ^ __funnelshift_r(m0, m1, 1);
    unsigned e1 = m1 ^ __funnelshift_r(m1, m2, 1);
    unsigned e2 = m2 ^ __funnelshift_r(m2, m3, 1);
    if (gl < 4)   e0 &= 0x7FFFFFFFu;      // fake transition guard|pixel0
    if (gl >= 60) e1 &= 0x7FFFFFFFu;      // fake transition pixel511|guard

    const int pb = (gl & 3) * 8;
    unsigned ow[4];
    #pragma unroll
    for (int jj = 0; jj < 4; ++jj) {
        const int p = pb + jj * 2;
        unsigned R32 = __funnelshift_r(e1, e2, p);
        unsigned L32 = __funnelshift_r(e0, e1, p);
        int rd = __ffs((int)(R32 | 0x80000000u));    // 1..32 (32 = far)
        int ld = __clz((int)(L32 | 1u)) + 1;         // 1..32 (32 = far)
        unsigned eA = (unsigned)min(rd, ld);
        unsigned pA = ((m1 >> p) & 1u) ? (eA << 8) : eA;

        unsigned R32b = __funnelshift_r(e1, e2, p + 1);
        unsigned L32b = __funnelshift_r(e0, e1, p + 1);
        int rdb = __ffs((int)(R32b | 0x80000000u));
        int ldb = __clz((int)(L32b | 1u)) + 1;
        unsigned eB = (unsigned)min(rdb, ldb);
        unsigned pB = ((m1 >> (p + 1)) & 1u) ? (eB << 8) : eB;

        ow[jj] = pA | (pB << 16);
    }
    ((uint4*)g_rcol)[(size_t)row * 64 + gl] = make_uint4(ow[0], ow[1], ow[2], ow[3]);
}

__device__ __forceinline__ uint4 vmin44(uint4 a, uint4 b) {
    return make_uint4(__vminu4(a.x, b.x), __vminu4(a.y, b.y),
                      __vminu4(a.z, b.z), __vminu4(a.w, b.w));
}
__device__ __forceinline__ uint4 vmax4s(uint4 a, unsigned d) {
    return make_uint4(__vmaxu4(a.x, d), __vmaxu4(a.y, d),
                      __vmaxu4(a.z, d), __vmaxu4(a.w, d));
}

// ---------------------------------------------------------------------------
// Kernel 2 (R12, measured best): vertical combine + softmax + weighted SE +
// block reduction. 4 rows/block, 256 thr, 8 px/thread; taps are 16B loads.
// ---------------------------------------------------------------------------
__global__ void __launch_bounds__(256)
loss_kernel(const float4* __restrict__ logits4) {
    const int o = threadIdx.x & 63;       // x-octet 0..63 (pixels 8o..8o+7)
    const int r = threadIdx.x >> 6;       // row in block 0..3
    const int y = blockIdx.y * 4 + r;
    const int b = blockIdx.z;

    // ---- independent loads up front: self + 4 taps + 8 logits ----
    const uint4* col = (const uint4*)g_rcol + (size_t)b * H * 64 + o;
    uint4 self = col[(size_t)y * 64];
    const uint4 FARQ = make_uint4(FARW, FARW, FARW, FARW);
    uint4 up1 = (y - 1 >= 0) ? col[(size_t)(y - 1) * 64] : FARQ;
    uint4 dn1 = (y + 1 <  H) ? col[(size_t)(y + 1) * 64] : FARQ;
    uint4 up2 = (y - 2 >= 0) ? col[(size_t)(y - 2) * 64] : FARQ;
    uint4 dn2 = (y + 2 <  H) ? col[(size_t)(y + 2) * 64] : FARQ;

    const float4* lp = logits4 + ((size_t)b * CHANS * H + y) * 128 + o * 2;
    float4 La0 = lp[0];
    float4 La1 = lp[(size_t)H * 128];
    float4 La2 = lp[2 * (size_t)H * 128];
    float4 La3 = lp[3 * (size_t)H * 128];
    float4 Lb0 = lp[1];
    float4 Lb1 = lp[(size_t)H * 128 + 1];
    float4 Lb2 = lp[2 * (size_t)H * 128 + 1];
    float4 Lb3 = lp[3 * (size_t)H * 128 + 1];

    // ---- softmax for all 8 pixels while taps fly ----
    float gp[8];
    {
        float l0[8] = {La0.x, La0.y, La0.z, La0.w, Lb0.x, Lb0.y, Lb0.z, Lb0.w};
        float l1[8] = {La1.x, La1.y, La1.z, La1.w, Lb1.x, Lb1.y, Lb1.z, Lb1.w};
        float l2[8] = {La2.x, La2.y, La2.z, La2.w, Lb2.x, Lb2.y, Lb2.z, Lb2.w};
        float l3[8] = {La3.x, La3.y, La3.z, La3.w, Lb3.x, Lb3.y, Lb3.z, Lb3.w};
        #pragma unroll
        for (int k = 0; k < 8; ++k) {
            float hi  = fmaxf(l1[k], l2[k]);
            float lo  = fminf(l1[k], l2[k]);
            float aa  = fmaxf(hi, l3[k]);
            float sec = fminf(hi, l3[k]);
            float sum = 1.0f + __expf(lo - aa) + __expf(sec - aa) + __expf(l0[k] - aa);
            gp[k] = 1.0f / sum;
        }
    }

    // ---- first double-step (d=1,2) unconditional with prefetched taps ----
    uint4 s = self;
    s = vmin44(s, vmin44(vmax4s(vmin44(up1, dn1), 0x01010101u),
                         vmax4s(vmin44(up2, dn2), 0x02020202u)));

    // ---- remaining double-steps with early exit ----
    #pragma unroll 1
    for (int d = 3; d <= 29; d += 2) {
        unsigned mm = __vmaxu4(__vmaxu4(s.x, s.y), __vmaxu4(s.z, s.w));
        if (((mm + (128 - d) * 0x01010101u) & 0x80808080u) == 0u) break; // all <= d-1
        uint4 u1 = (y - d     >= 0) ? col[(size_t)(y - d)     * 64] : FARQ;
        uint4 d1 = (y + d     <  H) ? col[(size_t)(y + d)     * 64] : FARQ;
        uint4 u2 = (y - d - 1 >= 0) ? col[(size_t)(y - d - 1) * 64] : FARQ;
        uint4 d2 = (y + d + 1 <  H) ? col[(size_t)(y + d + 1) * 64] : FARQ;
        unsigned dd1 = (unsigned)d * 0x01010101u;
        unsigned dd2 = dd1 + 0x01010101u;
        s = vmin44(s, vmin44(vmax4s(vmin44(u1, d1), dd1),
                             vmax4s(vmin44(u2, d2), dd2)));
    }

    // ---- combine: integer wmap, fp32 error ----
    unsigned sw[4] = {s.x, s.y, s.z, s.w};
    float v = 0.0f;
    #pragma unroll
    for (int k = 0; k < 8; ++k) {
        unsigned w = sw[k >> 1] >> (16 * (k & 1));
        unsigned f = w & 255u;
        unsigned g = (w >> 8) & 255u;
        int df2 = (f <= 30u) ? (int)(f * f) : 40000;
        int dg2 = (g <= 30u) ? (int)(g * g) : 40000;
        float wmap = (float)(df2 + dg2);
        float gt = (f == 0u) ? 1.0f : 0.0f;
        float diff = gp[k] - gt;
        v += diff * diff * wmap;
    }

    // ---- deterministic block reduction (8 warps) ----
    #pragma unroll
    for (int oo = 16; oo > 0; oo >>= 1) v += __shfl_down_sync(0xFFFFFFFFu, v, oo);
    __shared__ float wsum[8];
    int lane = threadIdx.x & 31, wid = threadIdx.x >> 5;
    if (lane == 0) wsum[wid] = v;
    __syncthreads();
    if (threadIdx.x == 0) {
        double sd = 0.0;
        #pragma unroll
        for (int i = 0; i < 8; ++i) sd += (double)wsum[i];
        g_bsum[blockIdx.z * gridDim.y + blockIdx.y] = sd;
    }
}

// Kernel 3 (R12): deterministic final reduction + mean.
__global__ void final_kernel(float* __restrict__ out) {
    __shared__ double sh[256];
    double s = 0.0;
    #pragma unroll
    for (int i = 0; i < LOSS_BLOCKS / 256; ++i)
        s += g_bsum[threadIdx.x + i * 256];
    sh[threadIdx.x] = s;
    __syncthreads();
    #pragma unroll
    for (int o = 128; o > 0; o >>= 1) {
        if (threadIdx.x < o) sh[threadIdx.x] += sh[threadIdx.x + o];
        __syncthreads();
    }
    if (threadIdx.x == 0) out[0] = (float)(sh[0] / (double)NPIX);
}

extern "C" void kernel_launch(void* const* d_in, const int* in_sizes, int n_in,
                              void* d_out, int out_size) {
    const float* logits = (const float*)d_in[0];
    const int*   y_true = (const int*)d_in[1];
    float*       out    = (float*)d_out;

    rowdist_kernel<<<NROWS / 4, 256>>>((const int4*)y_true);

    dim3 blk(256, 1, 1);
    dim3 grd(1, H / 4, BATCH);
    loss_kernel<<<grd, blk>>>((const float4*)logits);

    final_kernel<<<1, 256>>>(out);
}

// round 15
// speedup vs baseline: 1.1606x; 1.0345x over previous
#include <cuda_runtime.h>
#include <cuda_bf16.h>

#define BATCH 8
#define CHANS 4
#define H 512
#define W 512
#define NPIX (BATCH * H * W)          // 2,097,152
#define NROWS (BATCH * H)             // 4096
#define LOSS_BLOCKS (BATCH * (H / 4)) // 1024

typedef unsigned long long u64;
#define FARW 0x7f7f7f7fu

// Scratch: per-pixel horizontal distances (byte pairs: fg, bg).
__device__ uchar2 g_rcol[NPIX];
__device__ double g_bsum[LOSS_BLOCKS];

// ---------------------------------------------------------------------------
// Kernel 1 (R12 measured-best): horizontal distance to nearest opposite-class
// pixel. 4 rows/block (256 thr), 8 px/lane; 32-bit funnel-shift search.
// ---------------------------------------------------------------------------
__global__ void rowdist_kernel(const int4* __restrict__ yt4) {
    __shared__ unsigned m32[4][20];   // [0] guard, [1..16] mask, [17..19] guards
    const int tid = threadIdx.x;
    const int r  = tid >> 6;              // row in block 0..3
    const int gl = tid & 63;              // byte index, pixels 8gl..8gl+7
    const int row = blockIdx.x * 4 + r;

    const int4* pp = yt4 + (size_t)row * 128 + gl * 2;
    int4 a = pp[0], b = pp[1];

    unsigned ta = __byte_perm((unsigned)a.x, (unsigned)a.y, 0x4040);
    unsigned tb = __byte_perm((unsigned)a.z, (unsigned)a.w, 0x4040);
    unsigned ua = __byte_perm(ta, tb, 0x5410);
    unsigned tc = __byte_perm((unsigned)b.x, (unsigned)b.y, 0x4040);
    unsigned td = __byte_perm((unsigned)b.z, (unsigned)b.w, 0x4040);
    unsigned ub = __byte_perm(tc, td, 0x5410);
    ua = (ua | (ua >> 1)) & 0x01010101u;
    ub = (ub | (ub >> 1)) & 0x01010101u;
    unsigned m8 = (((ua * 0x01020408u) >> 24) & 0xFu)
                | (((ub * 0x01020408u) >> 20) & 0xF0u);

    if (tid < 4) { m32[tid][0] = 0u; }
    if (tid >= 4 && tid < 16) { m32[tid & 3][17 + (tid >> 2) - 1] = 0u; }
    ((unsigned char*)&m32[r][1])[gl] = (unsigned char)m8;
    __syncthreads();

    const unsigned* base = &m32[r][gl >> 2];
    unsigned m0 = base[0], m1 = base[1], m2 = base[2], m3 = base[3];
    unsigned e0 = m0 ^ __funnelshift_r(m0, m1, 1);
    unsigned e1 = m1 ^ __funnelshift_r(m1, m2, 1);
    unsigned e2 = m2 ^ __funnelshift_r(m2, m3, 1);
    if (gl < 4)   e0 &= 0x7FFFFFFFu;      // fake transition guard|pixel0
    if (gl >= 60) e1 &= 0x7FFFFFFFu;      // fake transition pixel511|guard

    const int pb = (gl & 3) * 8;
    u64 out[2] = {0ull, 0ull};
    #pragma unroll
    for (int j = 0; j < 8; ++j) {
        const int p = pb + j;
        unsigned R32 = __funnelshift_r(e1, e2, p);
        unsigned L32 = __funnelshift_r(e0, e1, p);
        int rd = __ffs((int)(R32 | 0x80000000u));    // 1..32 (32 = far)
        int ld = __clz((int)(L32 | 1u)) + 1;         // 1..32 (32 = far)
        unsigned e = (unsigned)min(rd, ld);
        unsigned pair = ((m1 >> p) & 1u) ? (e << 8) : e;
        out[j >> 2] |= (u64)pair << (16 * (j & 3));
    }
    ((ulonglong2*)g_rcol)[(size_t)row * 64 + gl] = make_ulonglong2(out[0], out[1]);
}

__device__ __forceinline__ uint4 vmin44(uint4 a, uint4 b) {
    return make_uint4(__vminu4(a.x, b.x), __vminu4(a.y, b.y),
                      __vminu4(a.z, b.z), __vminu4(a.w, b.w));
}
__device__ __forceinline__ uint4 vmax4s(uint4 a, unsigned d) {
    return make_uint4(__vmaxu4(a.x, d), __vmaxu4(a.y, d),
                      __vmaxu4(a.z, d), __vmaxu4(a.w, d));
}

// ---------------------------------------------------------------------------
// Kernel 2 (R12 measured-best): vertical combine + softmax + weighted SE +
// block reduction. 4 rows/block, 256 thr, 8 px/thread; taps are 16B loads.
// ---------------------------------------------------------------------------
__global__ void __launch_bounds__(256)
loss_kernel(const float4* __restrict__ logits4) {
    const int o = threadIdx.x & 63;       // x-octet 0..63 (pixels 8o..8o+7)
    const int r = threadIdx.x >> 6;       // row in block 0..3
    const int y = blockIdx.y * 4 + r;
    const int b = blockIdx.z;

    // ---- independent loads up front: self + 4 taps + 8 logits ----
    const uint4* col = (const uint4*)g_rcol + (size_t)b * H * 64 + o;
    uint4 self = col[(size_t)y * 64];
    const uint4 FARQ = make_uint4(FARW, FARW, FARW, FARW);
    uint4 up1 = (y - 1 >= 0) ? col[(size_t)(y - 1) * 64] : FARQ;
    uint4 dn1 = (y + 1 <  H) ? col[(size_t)(y + 1) * 64] : FARQ;
    uint4 up2 = (y - 2 >= 0) ? col[(size_t)(y - 2) * 64] : FARQ;
    uint4 dn2 = (y + 2 <  H) ? col[(size_t)(y + 2) * 64] : FARQ;

    const float4* lp = logits4 + ((size_t)b * CHANS * H + y) * 128 + o * 2;
    float4 La0 = lp[0];
    float4 La1 = lp[(size_t)H * 128];
    float4 La2 = lp[2 * (size_t)H * 128];
    float4 La3 = lp[3 * (size_t)H * 128];
    float4 Lb0 = lp[1];
    float4 Lb1 = lp[(size_t)H * 128 + 1];
    float4 Lb2 = lp[2 * (size_t)H * 128 + 1];
    float4 Lb3 = lp[3 * (size_t)H * 128 + 1];

    // ---- softmax for all 8 pixels while taps fly ----
    float gp[8];
    {
        float l0[8] = {La0.x, La0.y, La0.z, La0.w, Lb0.x, Lb0.y, Lb0.z, Lb0.w};
        float l1[8] = {La1.x, La1.y, La1.z, La1.w, Lb1.x, Lb1.y, Lb1.z, Lb1.w};
        float l2[8] = {La2.x, La2.y, La2.z, La2.w, Lb2.x, Lb2.y, Lb2.z, Lb2.w};
        float l3[8] = {La3.x, La3.y, La3.z, La3.w, Lb3.x, Lb3.y, Lb3.z, Lb3.w};
        #pragma unroll
        for (int k = 0; k < 8; ++k) {
            float hi  = fmaxf(l1[k], l2[k]);
            float lo  = fminf(l1[k], l2[k]);
            float aa  = fmaxf(hi, l3[k]);
            float sec = fminf(hi, l3[k]);
            float sum = 1.0f + __expf(lo - aa) + __expf(sec - aa) + __expf(l0[k] - aa);
            gp[k] = 1.0f / sum;
        }
    }

    // ---- first double-step (d=1,2) unconditional with prefetched taps ----
    uint4 s = self;
    s = vmin44(s, vmin44(vmax4s(vmin44(up1, dn1), 0x01010101u),
                         vmax4s(vmin44(up2, dn2), 0x02020202u)));

    // ---- remaining double-steps with early exit (all bytes <= d => done) ----
    #pragma unroll 1
    for (int d = 3; d <= 29; d += 2) {
        unsigned mm = __vmaxu4(__vmaxu4(s.x, s.y), __vmaxu4(s.z, s.w));
        if (((mm + (127 - d) * 0x01010101u) & 0x80808080u) == 0u) break; // all <= d
        uint4 u1 = (y - d     >= 0) ? col[(size_t)(y - d)     * 64] : FARQ;
        uint4 d1 = (y + d     <  H) ? col[(size_t)(y + d)     * 64] : FARQ;
        uint4 u2 = (y - d - 1 >= 0) ? col[(size_t)(y - d - 1) * 64] : FARQ;
        uint4 d2 = (y + d + 1 <  H) ? col[(size_t)(y + d + 1) * 64] : FARQ;
        unsigned dd1 = (unsigned)d * 0x01010101u;
        unsigned dd2 = dd1 + 0x01010101u;
        s = vmin44(s, vmin44(vmax4s(vmin44(u1, d1), dd1),
                             vmax4s(vmin44(u2, d2), dd2)));
    }

    // ---- combine: integer wmap, fp32 error ----
    unsigned sw[4] = {s.x, s.y, s.z, s.w};
    float v = 0.0f;
    #pragma unroll
    for (int k = 0; k < 8; ++k) {
        unsigned w = sw[k >> 1] >> (16 * (k & 1));
        unsigned f = w & 255u;
        unsigned g = (w >> 8) & 255u;
        int df2 = (f <= 30u) ? (int)(f * f) : 40000;
        int dg2 = (g <= 30u) ? (int)(g * g) : 40000;
        float wmap = (float)(df2 + dg2);
        float gt = (f == 0u) ? 1.0f : 0.0f;
        float diff = gp[k] - gt;
        v += diff * diff * wmap;
    }

    // ---- deterministic block reduction (8 warps) ----
    #pragma unroll
    for (int oo = 16; oo > 0; oo >>= 1) v += __shfl_down_sync(0xFFFFFFFFu, v, oo);
    __shared__ float wsum[8];
    int lane = threadIdx.x & 31, wid = threadIdx.x >> 5;
    if (lane == 0) wsum[wid] = v;
    __syncthreads();
    if (threadIdx.x == 0) {
        double sd = 0.0;
        #pragma unroll
        for (int i = 0; i < 8; ++i) sd += (double)wsum[i];
        g_bsum[blockIdx.z * gridDim.y + blockIdx.y] = sd;
    }
}

// Kernel 3: deterministic final reduction + mean (512 threads, 4 elems each).
__global__ void final_kernel(float* __restrict__ out) {
    __shared__ double sh[512];
    double s = 0.0;
    #pragma unroll
    for (int i = 0; i < LOSS_BLOCKS / 512; ++i)
        s += g_bsum[threadIdx.x + i * 512];
    sh[threadIdx.x] = s;
    __syncthreads();
    #pragma unroll
    for (int o = 256; o > 0; o >>= 1) {
        if (threadIdx.x < o) sh[threadIdx.x] += sh[threadIdx.x + o];
        __syncthreads();
    }
    if (threadIdx.x == 0) out[0] = (float)(sh[0] / (double)NPIX);
}

extern "C" void kernel_launch(void* const* d_in, const int* in_sizes, int n_in,
                              void* d_out, int out_size) {
    const float* logits = (const float*)d_in[0];
    const int*   y_true = (const int*)d_in[1];
    float*       out    = (float*)d_out;

    rowdist_kernel<<<NROWS / 4, 256>>>((const int4*)y_true);

    dim3 blk(256, 1, 1);
    dim3 grd(1, H / 4, BATCH);
    loss_kernel<<<grd, blk>>>((const float4*)logits);

    final_kernel<<<1, 512>>>(out);
}